// round 8
// baseline (speedup 1.0000x reference)
#include <cuda_runtime.h>
#include <cuda_fp16.h>
#include <math.h>

#define S_LEN   2048
#define BATCH   2
#define NHEAD   32
#define KVHEADS 8
#define HDIM    64
#define WIN     256
#define GROUP   4
#define QTILE   32
#define NC      64
#define QSTRIDE (NHEAD*HDIM)
#define KSTRIDE (KVHEADS*HDIM)
#define KROW    72
#define QH_HALVES    (128*KROW)
#define STAGE_HALVES (2*NC*KROW)
#define SMEM_BYTES   ((QH_HALVES + 2*STAGE_HALVES)*2)   // 55296 B

__device__ float g_cos[S_LEN * 32];
__device__ float g_sin[S_LEN * 32];

__device__ __align__(16) __half Khalf[(size_t)BATCH * KVHEADS * S_LEN * HDIM];
__device__ __align__(16) __half Vhalf[(size_t)BATCH * KVHEADS * S_LEN * HDIM];

// Fused: K RoPE + fp16 convert + V convert; (b==0,kh==0) threads persist the
// cos/sin table for attn's Q RoPE. inv_freq via exp2f (single MUFU).
__global__ void prep_kv_kernel(const float* __restrict__ K, const float* __restrict__ V) {
    int idx = blockIdx.x * blockDim.x + threadIdx.x;
    if (idx >= BATCH * S_LEN * KVHEADS * 32) return;
    int d  = idx & 31;
    int kh = (idx >> 5) & 7;
    int s  = (idx >> 8) & 2047;
    int b  = idx >> 19;

    // 10000^(-d/32) = 2^(-d * log2(10000)/32)
    float inv = exp2f((float)d * -0.4152410118923361f);
    float sn, c;
    sincosf((float)s * inv, &sn, &c);
    if ((b | kh) == 0) {
        g_cos[s * 32 + d] = c;
        g_sin[s * 32 + d] = sn;
    }

    size_t ioff = (size_t)(b * S_LEN + s) * KSTRIDE + kh * HDIM + d;
    size_t ooff = ((size_t)(b * KVHEADS + kh) * S_LEN + s) * HDIM + d;
    float x = K[ioff], y = K[ioff + 32];
    Khalf[ooff]      = __float2half(x * c - y * sn);
    Khalf[ooff + 32] = __float2half(y * c + x * sn);
    Vhalf[ooff]      = __float2half(V[ioff]);
    Vhalf[ooff + 32] = __float2half(V[ioff + 32]);
}

__device__ __forceinline__ unsigned smem_u32(const void* p) {
    return (unsigned)__cvta_generic_to_shared(p);
}
__device__ __forceinline__ void ldsm_x4(unsigned& r0, unsigned& r1, unsigned& r2, unsigned& r3, unsigned a) {
    asm volatile("ldmatrix.sync.aligned.m8n8.x4.shared.b16 {%0,%1,%2,%3}, [%4];"
                 : "=r"(r0), "=r"(r1), "=r"(r2), "=r"(r3) : "r"(a));
}
__device__ __forceinline__ void ldsm_x4_t(unsigned& r0, unsigned& r1, unsigned& r2, unsigned& r3, unsigned a) {
    asm volatile("ldmatrix.sync.aligned.m8n8.x4.trans.shared.b16 {%0,%1,%2,%3}, [%4];"
                 : "=r"(r0), "=r"(r1), "=r"(r2), "=r"(r3) : "r"(a));
}
__device__ __forceinline__ void mma16816(float* c, const unsigned* a, unsigned b0, unsigned b1) {
    asm volatile("mma.sync.aligned.m16n8k16.row.col.f32.f16.f16.f32 "
                 "{%0,%1,%2,%3}, {%4,%5,%6,%7}, {%8,%9}, {%0,%1,%2,%3};"
                 : "+f"(c[0]), "+f"(c[1]), "+f"(c[2]), "+f"(c[3])
                 : "r"(a[0]), "r"(a[1]), "r"(a[2]), "r"(a[3]), "r"(b0), "r"(b1));
}
__device__ __forceinline__ unsigned packh2(float lo, float hi) {
    __half2 h = __floats2half2_rn(lo, hi);
    return *reinterpret_cast<unsigned*>(&h);
}
__device__ __forceinline__ void cp16(unsigned dst, const void* src) {
    asm volatile("cp.async.cg.shared.global [%0], [%1], 16;" :: "r"(dst), "l"(src));
}
__device__ __forceinline__ void cp_commit() {
    asm volatile("cp.async.commit_group;");
}
template<int N> __device__ __forceinline__ void cp_wait() {
    asm volatile("cp.async.wait_group %0;" :: "n"(N));
}

__global__ void __launch_bounds__(256, 2)
attn_kernel(const float* __restrict__ Q, float* __restrict__ O)
{
    extern __shared__ __align__(16) __half sm[];
    __half* qhbuf = sm;                              // dedicated Q tile region
    const unsigned kvsm = smem_u32(sm + QH_HALVES);  // 2 K|V stages after it

    const int tid  = threadIdx.x;
    const int w    = tid >> 5;
    const int lane = tid & 31;
    const int g    = lane >> 2;
    const int t    = lane & 3;
    const int qh_i = w & 1;
    const int hl   = w >> 1;
    const int qs   = blockIdx.x * QTILE;
    const int kvh  = blockIdx.y;
    const int b    = blockIdx.z;

    // RoPE Q: fp32 gmem -> fp16 smem, 2 threads/row
    {
        int r    = tid >> 1;
        int half = tid & 1;
        int qg   = qs + (r & 31);
        const float* qp = Q + ((size_t)(b * S_LEN + qg) * QSTRIDE
                               + (kvh * GROUP + (r >> 5)) * HDIM);
        const float* ct = g_cos + qg * 32;
        const float* st = g_sin + qg * 32;
        __half* row = qhbuf + r * KROW;
        #pragma unroll
        for (int j4 = 0; j4 < 4; ++j4) {
            int d = half * 16 + j4 * 4;
            float4 x = *reinterpret_cast<const float4*>(qp + d);
            float4 y = *reinterpret_cast<const float4*>(qp + d + 32);
            float c0 = ct[d], c1 = ct[d+1], c2 = ct[d+2], c3 = ct[d+3];
            float s0 = st[d], s1 = st[d+1], s2 = st[d+2], s3 = st[d+3];
            __half2* lo = reinterpret_cast<__half2*>(row + d);
            __half2* hi = reinterpret_cast<__half2*>(row + d + 32);
            lo[0] = __floats2half2_rn((x.x*c0 - y.x*s0)*0.125f, (x.y*c1 - y.y*s1)*0.125f);
            lo[1] = __floats2half2_rn((x.z*c2 - y.z*s2)*0.125f, (x.w*c3 - y.w*s3)*0.125f);
            hi[0] = __floats2half2_rn((y.x*c0 + x.x*s0)*0.125f, (y.y*c1 + x.y*s1)*0.125f);
            hi[1] = __floats2half2_rn((y.z*c2 + x.z*s2)*0.125f, (y.w*c3 + x.w*s3)*0.125f);
        }
    }
    __syncthreads();

    unsigned qa[4][4];
    {
        unsigned qbase = smem_u32(qhbuf);
        int row  = hl * 32 + qh_i * 16 + (lane & 15);
        int colh = (lane >> 4) * 8;
        #pragma unroll
        for (int ki = 0; ki < 4; ++ki) {
            unsigned a = qbase + (unsigned)((row * KROW + ki * 16 + colh) * 2);
            ldsm_x4(qa[ki][0], qa[ki][1], qa[ki][2], qa[ki][3], a);
        }
    }

    float of[8][4];
    #pragma unroll
    for (int n = 0; n < 8; ++n)
        #pragma unroll
        for (int e = 0; e < 4; ++e) of[n][e] = 0.f;
    float lsum[2] = {0.f, 0.f};

    const int qgmin = qs + qh_i * 16;
    const int qgmax = qgmin + 15;
    const int j0  = (qs >= WIN) ? ((qs - WIN) & ~(NC - 1)) : 0;
    const int nch = (qs + QTILE - j0 + NC - 1) / NC;

    const __half* ksrc = Khalf + ((size_t)(b * KVHEADS + kvh) * S_LEN) * HDIM;
    const __half* vsrc = Vhalf + ((size_t)(b * KVHEADS + kvh) * S_LEN) * HDIM;

    const int kb_key = ((lane >> 4) & 1) * 8 + (lane & 7);
    const int kb_dim = ((lane >> 3) & 1) * 8;
    const int vb_key = ((lane >> 3) & 1) * 8 + (lane & 7);
    const int vb_dim = ((lane >> 4) & 1) * 8;

    auto stage_load = [&](int ci, int s) {
        int c0 = j0 + ci * NC;
        unsigned base = kvsm + (unsigned)(s * STAGE_HALVES * 2);
        #pragma unroll
        for (int it = 0; it < 4; ++it) {
            int idx = tid + it * 256;
            int tensor = idx >> 9;
            int r = (idx >> 3) & 63, p = idx & 7;
            const __half* src = (tensor ? vsrc : ksrc) + (size_t)(c0 + r) * HDIM + p * 8;
            unsigned dst = base + (unsigned)((tensor * NC * KROW + r * KROW + p * 8) * 2);
            cp16(dst, src);
        }
        cp_commit();
    };

    stage_load(0, 0);

    for (int ci = 0; ci < nch; ++ci) {
        if (ci + 1 < nch) { stage_load(ci + 1, (ci + 1) & 1); cp_wait<1>(); }
        else              { cp_wait<0>(); }
        __syncthreads();

        const unsigned ks = kvsm + (unsigned)(((ci & 1) * STAGE_HALVES) * 2);
        const unsigned vs = ks + (unsigned)(NC * KROW * 2);
        const int c0 = j0 + ci * NC;

        #pragma unroll
        for (int np = 0; np < 4; ++np) {
            const int colbase = c0 + np * 16;
            if (colbase > qgmax || colbase + 15 + WIN < qgmin) continue;

            unsigned kb[4][4];
            #pragma unroll
            for (int ki = 0; ki < 4; ++ki) {
                unsigned a = ks + (unsigned)((((np * 16 + kb_key) * KROW) + ki * 16 + kb_dim) * 2);
                ldsm_x4(kb[ki][0], kb[ki][1], kb[ki][2], kb[ki][3], a);
            }
            float sf[2][4];
            #pragma unroll
            for (int ni = 0; ni < 2; ++ni)
                #pragma unroll
                for (int e = 0; e < 4; ++e) sf[ni][e] = 0.f;
            #pragma unroll
            for (int ki = 0; ki < 4; ++ki) {
                mma16816(sf[0], qa[ki], kb[ki][0], kb[ki][1]);
                mma16816(sf[1], qa[ki], kb[ki][2], kb[ki][3]);
            }

            const int qg0 = qgmin + g;
            const int qg1 = qg0 + 8;
            unsigned pa[4];
            const bool full = (colbase + 15 <= qgmin) && (colbase >= qgmax - WIN);
            if (full) {
                #pragma unroll
                for (int ni = 0; ni < 2; ++ni) {
                    float e00 = __expf(sf[ni][0]);
                    float e01 = __expf(sf[ni][1]);
                    float e10 = __expf(sf[ni][2]);
                    float e11 = __expf(sf[ni][3]);
                    lsum[0] += e00 + e01;
                    lsum[1] += e10 + e11;
                    pa[ni * 2 + 0] = packh2(e00, e01);
                    pa[ni * 2 + 1] = packh2(e10, e11);
                }
            } else {
                #pragma unroll
                for (int ni = 0; ni < 2; ++ni) {
                    int p0 = colbase + ni * 8 + 2 * t;
                    int p1 = p0 + 1;
                    float e00 = (p0 <= qg0 && p0 + WIN >= qg0) ? __expf(sf[ni][0]) : 0.f;
                    float e01 = (p1 <= qg0 && p1 + WIN >= qg0) ? __expf(sf[ni][1]) : 0.f;
                    float e10 = (p0 <= qg1 && p0 + WIN >= qg1) ? __expf(sf[ni][2]) : 0.f;
                    float e11 = (p1 <= qg1 && p1 + WIN >= qg1) ? __expf(sf[ni][3]) : 0.f;
                    lsum[0] += e00 + e01;
                    lsum[1] += e10 + e11;
                    pa[ni * 2 + 0] = packh2(e00, e01);
                    pa[ni * 2 + 1] = packh2(e10, e11);
                }
            }

            unsigned vb[4][4];
            #pragma unroll
            for (int dp = 0; dp < 4; ++dp) {
                unsigned a = vs + (unsigned)((((np * 16 + vb_key) * KROW) + dp * 16 + vb_dim) * 2);
                ldsm_x4_t(vb[dp][0], vb[dp][1], vb[dp][2], vb[dp][3], a);
            }
            #pragma unroll
            for (int dp = 0; dp < 4; ++dp) {
                mma16816(of[2 * dp],     pa, vb[dp][0], vb[dp][1]);
                mma16816(of[2 * dp + 1], pa, vb[dp][2], vb[dp][3]);
            }
        }
        __syncthreads();
    }

    #pragma unroll
    for (int i = 0; i < 2; ++i) {
        float v = lsum[i];
        v += __shfl_xor_sync(0xffffffffu, v, 1);
        v += __shfl_xor_sync(0xffffffffu, v, 2);
        lsum[i] = 1.f / v;
    }
    const int head = kvh * GROUP + hl;
    float* obase = O + (size_t)(b * S_LEN) * QSTRIDE + head * HDIM;
    const int r0 = qgmin + g;
    const int r1 = r0 + 8;
    #pragma unroll
    for (int n = 0; n < 8; ++n) {
        int col = n * 8 + 2 * t;
        float2 v0 = make_float2(of[n][0] * lsum[0], of[n][1] * lsum[0]);
        float2 v1 = make_float2(of[n][2] * lsum[1], of[n][3] * lsum[1]);
        *reinterpret_cast<float2*>(obase + (size_t)r0 * QSTRIDE + col) = v0;
        *reinterpret_cast<float2*>(obase + (size_t)r1 * QSTRIDE + col) = v1;
    }
}

extern "C" void kernel_launch(void* const* d_in, const int* in_sizes, int n_in,
                              void* d_out, int out_size) {
    const float* Q = (const float*)d_in[0];
    const float* K = (const float*)d_in[1];
    const float* V = (const float*)d_in[2];
    float* O = (float*)d_out;

    cudaFuncSetAttribute(attn_kernel, cudaFuncAttributeMaxDynamicSharedMemorySize, SMEM_BYTES);

    prep_kv_kernel<<<(BATCH * S_LEN * KVHEADS * 32 + 255) / 256, 256>>>(K, V);

    dim3 grid(S_LEN / QTILE, KVHEADS, BATCH);
    attn_kernel<<<grid, 256, SMEM_BYTES>>>(Q, O);
}

// round 9
// speedup vs baseline: 1.0486x; 1.0486x over previous
#include <cuda_runtime.h>
#include <cuda_fp16.h>
#include <math.h>

#define S_LEN   2048
#define BATCH   2
#define NHEAD   32
#define KVHEADS 8
#define HDIM    64
#define WIN     256
#define GROUP   4
#define QTILE   32
#define NC      64
#define QSTRIDE (NHEAD*HDIM)
#define KSTRIDE (KVHEADS*HDIM)
#define KROW    72
#define STAGE_HALVES (2*NC*KROW)
// Q staging overlays stage 0; steady state = 2 stages. 73728 B -> 3 CTAs/SM
#define SMEM_BYTES   (2*STAGE_HALVES*2)

// 0.125 * log2(e): scores come out of QK^T already in log2 domain
#define QSCALE 0.18033688011112042f

__device__ float g_cos[S_LEN * 32];
__device__ float g_sin[S_LEN * 32];

__device__ __align__(16) __half Khalf[(size_t)BATCH * KVHEADS * S_LEN * HDIM];
__device__ __align__(16) __half Vhalf[(size_t)BATCH * KVHEADS * S_LEN * HDIM];

// Fused K RoPE + fp16 convert + V convert; (b==0,kh==0) threads persist cos/sin.
__global__ void prep_kv_kernel(const float* __restrict__ K, const float* __restrict__ V) {
    int idx = blockIdx.x * blockDim.x + threadIdx.x;
    if (idx >= BATCH * S_LEN * KVHEADS * 32) return;
    int d  = idx & 31;
    int kh = (idx >> 5) & 7;
    int s  = (idx >> 8) & 2047;
    int b  = idx >> 19;

    float inv = exp2f((float)d * -0.4152410118923361f);   // 10000^(-d/32)
    float sn, c;
    sincosf((float)s * inv, &sn, &c);
    if ((b | kh) == 0) {
        g_cos[s * 32 + d] = c;
        g_sin[s * 32 + d] = sn;
    }

    size_t ioff = (size_t)(b * S_LEN + s) * KSTRIDE + kh * HDIM + d;
    size_t ooff = ((size_t)(b * KVHEADS + kh) * S_LEN + s) * HDIM + d;
    float x = K[ioff], y = K[ioff + 32];
    Khalf[ooff]      = __float2half(x * c - y * sn);
    Khalf[ooff + 32] = __float2half(y * c + x * sn);
    Vhalf[ooff]      = __float2half(V[ioff]);
    Vhalf[ooff + 32] = __float2half(V[ioff + 32]);
}

__device__ __forceinline__ unsigned smem_u32(const void* p) {
    return (unsigned)__cvta_generic_to_shared(p);
}
__device__ __forceinline__ void ldsm_x4(unsigned& r0, unsigned& r1, unsigned& r2, unsigned& r3, unsigned a) {
    asm volatile("ldmatrix.sync.aligned.m8n8.x4.shared.b16 {%0,%1,%2,%3}, [%4];"
                 : "=r"(r0), "=r"(r1), "=r"(r2), "=r"(r3) : "r"(a));
}
__device__ __forceinline__ void ldsm_x4_t(unsigned& r0, unsigned& r1, unsigned& r2, unsigned& r3, unsigned a) {
    asm volatile("ldmatrix.sync.aligned.m8n8.x4.trans.shared.b16 {%0,%1,%2,%3}, [%4];"
                 : "=r"(r0), "=r"(r1), "=r"(r2), "=r"(r3) : "r"(a));
}
__device__ __forceinline__ void mma16816(float* c, const unsigned* a, unsigned b0, unsigned b1) {
    asm volatile("mma.sync.aligned.m16n8k16.row.col.f32.f16.f16.f32 "
                 "{%0,%1,%2,%3}, {%4,%5,%6,%7}, {%8,%9}, {%0,%1,%2,%3};"
                 : "+f"(c[0]), "+f"(c[1]), "+f"(c[2]), "+f"(c[3])
                 : "r"(a[0]), "r"(a[1]), "r"(a[2]), "r"(a[3]), "r"(b0), "r"(b1));
}
__device__ __forceinline__ unsigned packh2(float lo, float hi) {
    __half2 h = __floats2half2_rn(lo, hi);
    return *reinterpret_cast<unsigned*>(&h);
}
// 2^x on packed fp16 pair — one XU op for two exps
__device__ __forceinline__ unsigned h2ex2(unsigned x) {
    unsigned d;
    asm("ex2.approx.f16x2 %0, %1;" : "=r"(d) : "r"(x));
    return d;
}
__device__ __forceinline__ unsigned hadd2u(unsigned a, unsigned b) {
    __half2 r = __hadd2(*reinterpret_cast<__half2*>(&a), *reinterpret_cast<__half2*>(&b));
    return *reinterpret_cast<unsigned*>(&r);
}
__device__ __forceinline__ void cp16(unsigned dst, const void* src) {
    asm volatile("cp.async.cg.shared.global [%0], [%1], 16;" :: "r"(dst), "l"(src));
}
__device__ __forceinline__ void cp_commit() {
    asm volatile("cp.async.commit_group;");
}
template<int N> __device__ __forceinline__ void cp_wait() {
    asm volatile("cp.async.wait_group %0;" :: "n"(N));
}

__global__ void __launch_bounds__(256, 3)
attn_kernel(const float* __restrict__ Q, float* __restrict__ O)
{
    extern __shared__ __align__(16) __half sm[];
    __half* qhbuf = sm;                    // transient Q staging (overlays stage 0)
    const unsigned kvsm = smem_u32(sm);

    const int tid  = threadIdx.x;
    const int w    = tid >> 5;
    const int lane = tid & 31;
    const int g    = lane >> 2;
    const int t    = lane & 3;
    const int qh_i = w & 1;
    const int hl   = w >> 1;
    const int qs   = blockIdx.x * QTILE;
    const int kvh  = blockIdx.y;
    const int b    = blockIdx.z;

    // RoPE Q: fp32 gmem -> fp16 smem (scaled by 0.125*log2e), 2 threads/row
    {
        int r    = tid >> 1;
        int half = tid & 1;
        int qg   = qs + (r & 31);
        const float* qp = Q + ((size_t)(b * S_LEN + qg) * QSTRIDE
                               + (kvh * GROUP + (r >> 5)) * HDIM);
        const float* ct = g_cos + qg * 32;
        const float* st = g_sin + qg * 32;
        __half* row = qhbuf + r * KROW;
        #pragma unroll
        for (int j4 = 0; j4 < 4; ++j4) {
            int d = half * 16 + j4 * 4;
            float4 x = *reinterpret_cast<const float4*>(qp + d);
            float4 y = *reinterpret_cast<const float4*>(qp + d + 32);
            float c0 = ct[d], c1 = ct[d+1], c2 = ct[d+2], c3 = ct[d+3];
            float s0 = st[d], s1 = st[d+1], s2 = st[d+2], s3 = st[d+3];
            __half2* lo = reinterpret_cast<__half2*>(row + d);
            __half2* hi = reinterpret_cast<__half2*>(row + d + 32);
            lo[0] = __floats2half2_rn((x.x*c0 - y.x*s0)*QSCALE, (x.y*c1 - y.y*s1)*QSCALE);
            lo[1] = __floats2half2_rn((x.z*c2 - y.z*s2)*QSCALE, (x.w*c3 - y.w*s3)*QSCALE);
            hi[0] = __floats2half2_rn((y.x*c0 + x.x*s0)*QSCALE, (y.y*c1 + x.y*s1)*QSCALE);
            hi[1] = __floats2half2_rn((y.z*c2 + x.z*s2)*QSCALE, (y.w*c3 + x.w*s3)*QSCALE);
        }
    }
    __syncthreads();

    unsigned qa[4][4];
    {
        unsigned qbase = smem_u32(qhbuf);
        int row  = hl * 32 + qh_i * 16 + (lane & 15);
        int colh = (lane >> 4) * 8;
        #pragma unroll
        for (int ki = 0; ki < 4; ++ki) {
            unsigned a = qbase + (unsigned)((row * KROW + ki * 16 + colh) * 2);
            ldsm_x4(qa[ki][0], qa[ki][1], qa[ki][2], qa[ki][3], a);
        }
    }
    __syncthreads();   // all warps done reading Q; stage 0 may overwrite it

    float of[8][4];
    #pragma unroll
    for (int n = 0; n < 8; ++n)
        #pragma unroll
        for (int e = 0; e < 4; ++e) of[n][e] = 0.f;
    float lsum[2] = {0.f, 0.f};

    const int qgmin = qs + qh_i * 16;
    const int qgmax = qgmin + 15;
    const int j0  = (qs >= WIN) ? ((qs - WIN) & ~(NC - 1)) : 0;
    const int nch = (qs + QTILE - j0 + NC - 1) / NC;

    const __half* ksrc = Khalf + ((size_t)(b * KVHEADS + kvh) * S_LEN) * HDIM;
    const __half* vsrc = Vhalf + ((size_t)(b * KVHEADS + kvh) * S_LEN) * HDIM;

    const int kb_key = ((lane >> 4) & 1) * 8 + (lane & 7);
    const int kb_dim = ((lane >> 3) & 1) * 8;
    const int vb_key = ((lane >> 3) & 1) * 8 + (lane & 7);
    const int vb_dim = ((lane >> 4) & 1) * 8;

    auto stage_load = [&](int ci, int s) {
        int c0 = j0 + ci * NC;
        unsigned base = kvsm + (unsigned)(s * STAGE_HALVES * 2);
        #pragma unroll
        for (int it = 0; it < 4; ++it) {
            int idx = tid + it * 256;
            int tensor = idx >> 9;
            int r = (idx >> 3) & 63, p = idx & 7;
            const __half* src = (tensor ? vsrc : ksrc) + (size_t)(c0 + r) * HDIM + p * 8;
            unsigned dst = base + (unsigned)((tensor * NC * KROW + r * KROW + p * 8) * 2);
            cp16(dst, src);
        }
        cp_commit();
    };

    stage_load(0, 0);

    for (int ci = 0; ci < nch; ++ci) {
        if (ci + 1 < nch) { stage_load(ci + 1, (ci + 1) & 1); cp_wait<1>(); }
        else              { cp_wait<0>(); }
        __syncthreads();

        const unsigned ks = kvsm + (unsigned)(((ci & 1) * STAGE_HALVES) * 2);
        const unsigned vs = ks + (unsigned)(NC * KROW * 2);
        const int c0 = j0 + ci * NC;

        unsigned l2[2] = {0u, 0u};   // per-chunk fp16x2 partial row sums

        #pragma unroll
        for (int np = 0; np < 4; ++np) {
            const int colbase = c0 + np * 16;
            if (colbase > qgmax || colbase + 15 + WIN < qgmin) continue;

            unsigned kb[4][4];
            #pragma unroll
            for (int ki = 0; ki < 4; ++ki) {
                unsigned a = ks + (unsigned)((((np * 16 + kb_key) * KROW) + ki * 16 + kb_dim) * 2);
                ldsm_x4(kb[ki][0], kb[ki][1], kb[ki][2], kb[ki][3], a);
            }
            float sf[2][4];
            #pragma unroll
            for (int ni = 0; ni < 2; ++ni)
                #pragma unroll
                for (int e = 0; e < 4; ++e) sf[ni][e] = 0.f;
            #pragma unroll
            for (int ki = 0; ki < 4; ++ki) {
                mma16816(sf[0], qa[ki], kb[ki][0], kb[ki][1]);
                mma16816(sf[1], qa[ki], kb[ki][2], kb[ki][3]);
            }

            const int qg0 = qgmin + g;
            const int qg1 = qg0 + 8;
            unsigned pa[4];
            const bool full = (colbase + 15 <= qgmin) && (colbase >= qgmax - WIN);
            if (!full) {
                // mask in log2 domain: invalid -> -inf (via -1e30 f32 -> f16 -inf)
                #pragma unroll
                for (int ni = 0; ni < 2; ++ni) {
                    int p0 = colbase + ni * 8 + 2 * t;
                    int p1 = p0 + 1;
                    sf[ni][0] = (p0 <= qg0 && p0 + WIN >= qg0) ? sf[ni][0] : -1e30f;
                    sf[ni][1] = (p1 <= qg0 && p1 + WIN >= qg0) ? sf[ni][1] : -1e30f;
                    sf[ni][2] = (p0 <= qg1 && p0 + WIN >= qg1) ? sf[ni][2] : -1e30f;
                    sf[ni][3] = (p1 <= qg1 && p1 + WIN >= qg1) ? sf[ni][3] : -1e30f;
                }
            }
            #pragma unroll
            for (int ni = 0; ni < 2; ++ni) {
                pa[ni * 2 + 0] = h2ex2(packh2(sf[ni][0], sf[ni][1]));   // row qg0
                pa[ni * 2 + 1] = h2ex2(packh2(sf[ni][2], sf[ni][3]));   // row qg1
                l2[0] = hadd2u(l2[0], pa[ni * 2 + 0]);
                l2[1] = hadd2u(l2[1], pa[ni * 2 + 1]);
            }

            unsigned vb[4][4];
            #pragma unroll
            for (int dp = 0; dp < 4; ++dp) {
                unsigned a = vs + (unsigned)((((np * 16 + vb_key) * KROW) + dp * 16 + vb_dim) * 2);
                ldsm_x4_t(vb[dp][0], vb[dp][1], vb[dp][2], vb[dp][3], a);
            }
            #pragma unroll
            for (int dp = 0; dp < 4; ++dp) {
                mma16816(of[2 * dp],     pa, vb[dp][0], vb[dp][1]);
                mma16816(of[2 * dp + 1], pa, vb[dp][2], vb[dp][3]);
            }
        }

        // flush per-chunk fp16 partial sums into fp32 accumulators
        #pragma unroll
        for (int i = 0; i < 2; ++i) {
            __half2 h = *reinterpret_cast<__half2*>(&l2[i]);
            lsum[i] += __low2float(h) + __high2float(h);
        }
        __syncthreads();
    }

    #pragma unroll
    for (int i = 0; i < 2; ++i) {
        float v = lsum[i];
        v += __shfl_xor_sync(0xffffffffu, v, 1);
        v += __shfl_xor_sync(0xffffffffu, v, 2);
        lsum[i] = 1.f / v;
    }
    const int head = kvh * GROUP + hl;
    float* obase = O + (size_t)(b * S_LEN) * QSTRIDE + head * HDIM;
    const int r0 = qgmin + g;
    const int r1 = r0 + 8;
    #pragma unroll
    for (int n = 0; n < 8; ++n) {
        int col = n * 8 + 2 * t;
        float2 v0 = make_float2(of[n][0] * lsum[0], of[n][1] * lsum[0]);
        float2 v1 = make_float2(of[n][2] * lsum[1], of[n][3] * lsum[1]);
        *reinterpret_cast<float2*>(obase + (size_t)r0 * QSTRIDE + col) = v0;
        *reinterpret_cast<float2*>(obase + (size_t)r1 * QSTRIDE + col) = v1;
    }
}

extern "C" void kernel_launch(void* const* d_in, const int* in_sizes, int n_in,
                              void* d_out, int out_size) {
    const float* Q = (const float*)d_in[0];
    const float* K = (const float*)d_in[1];
    const float* V = (const float*)d_in[2];
    float* O = (float*)d_out;

    cudaFuncSetAttribute(attn_kernel, cudaFuncAttributeMaxDynamicSharedMemorySize, SMEM_BYTES);

    prep_kv_kernel<<<(BATCH * S_LEN * KVHEADS * 32 + 255) / 256, 256>>>(K, V);

    dim3 grid(S_LEN / QTILE, KVHEADS, BATCH);
    attn_kernel<<<grid, 256, SMEM_BYTES>>>(Q, O);
}

// round 10
// speedup vs baseline: 1.2221x; 1.1654x over previous
#include <cuda_runtime.h>
#include <cuda_fp16.h>
#include <math.h>

#define S_LEN   2048
#define BATCH   2
#define NHEAD   32
#define KVHEADS 8
#define HDIM    64
#define WIN     256
#define GROUP   4
#define QTILE   32
#define NC      64
#define QSTRIDE (NHEAD*HDIM)
#define KSTRIDE (KVHEADS*HDIM)
#define KROW    72
#define STAGE_HALVES (2*NC*KROW)
// Q staging (128*KROW=18KB) overlays the 2 stages (36KB). 3 CTAs/SM.
#define SMEM_BYTES   (2*STAGE_HALVES*2)

// 0.125 * log2(e): scores come out of QK^T in log2 domain
#define QSCALE 0.18033688011112042f

__device__ float g_cos[S_LEN * 32];
__device__ float g_sin[S_LEN * 32];

__device__ __align__(16) __half Khalf[(size_t)BATCH * KVHEADS * S_LEN * HDIM];
__device__ __align__(16) __half Vhalf[(size_t)BATCH * KVHEADS * S_LEN * HDIM];

__global__ void prep_kv_kernel(const float* __restrict__ K, const float* __restrict__ V) {
    int idx = blockIdx.x * blockDim.x + threadIdx.x;
    if (idx >= BATCH * S_LEN * KVHEADS * 32) return;
    int d  = idx & 31;
    int kh = (idx >> 5) & 7;
    int s  = (idx >> 8) & 2047;
    int b  = idx >> 19;

    float inv = exp2f((float)d * -0.4152410118923361f);   // 10000^(-d/32)
    float sn, c;
    sincosf((float)s * inv, &sn, &c);
    if ((b | kh) == 0) {
        g_cos[s * 32 + d] = c;
        g_sin[s * 32 + d] = sn;
    }

    size_t ioff = (size_t)(b * S_LEN + s) * KSTRIDE + kh * HDIM + d;
    size_t ooff = ((size_t)(b * KVHEADS + kh) * S_LEN + s) * HDIM + d;
    float x = K[ioff], y = K[ioff + 32];
    Khalf[ooff]      = __float2half(x * c - y * sn);
    Khalf[ooff + 32] = __float2half(y * c + x * sn);
    Vhalf[ooff]      = __float2half(V[ioff]);
    Vhalf[ooff + 32] = __float2half(V[ioff + 32]);
}

__device__ __forceinline__ unsigned smem_u32(const void* p) {
    return (unsigned)__cvta_generic_to_shared(p);
}
__device__ __forceinline__ void ldsm_x4(unsigned& r0, unsigned& r1, unsigned& r2, unsigned& r3, unsigned a) {
    asm volatile("ldmatrix.sync.aligned.m8n8.x4.shared.b16 {%0,%1,%2,%3}, [%4];"
                 : "=r"(r0), "=r"(r1), "=r"(r2), "=r"(r3) : "r"(a));
}
__device__ __forceinline__ void ldsm_x4_t(unsigned& r0, unsigned& r1, unsigned& r2, unsigned& r3, unsigned a) {
    asm volatile("ldmatrix.sync.aligned.m8n8.x4.trans.shared.b16 {%0,%1,%2,%3}, [%4];"
                 : "=r"(r0), "=r"(r1), "=r"(r2), "=r"(r3) : "r"(a));
}
__device__ __forceinline__ void mma16816(float* c, const unsigned* a, unsigned b0, unsigned b1) {
    asm volatile("mma.sync.aligned.m16n8k16.row.col.f32.f16.f16.f32 "
                 "{%0,%1,%2,%3}, {%4,%5,%6,%7}, {%8,%9}, {%0,%1,%2,%3};"
                 : "+f"(c[0]), "+f"(c[1]), "+f"(c[2]), "+f"(c[3])
                 : "r"(a[0]), "r"(a[1]), "r"(a[2]), "r"(a[3]), "r"(b0), "r"(b1));
}
__device__ __forceinline__ unsigned packh2(float lo, float hi) {
    __half2 h = __floats2half2_rn(lo, hi);
    return *reinterpret_cast<unsigned*>(&h);
}
__device__ __forceinline__ unsigned h2ex2(unsigned x) {
    unsigned d;
    asm("ex2.approx.f16x2 %0, %1;" : "=r"(d) : "r"(x));
    return d;
}
__device__ __forceinline__ unsigned hadd2u(unsigned a, unsigned b) {
    __half2 r = __hadd2(*reinterpret_cast<__half2*>(&a), *reinterpret_cast<__half2*>(&b));
    return *reinterpret_cast<unsigned*>(&r);
}
__device__ __forceinline__ void cp16(unsigned dst, const void* src) {
    asm volatile("cp.async.cg.shared.global [%0], [%1], 16;" :: "r"(dst), "l"(src));
}
__device__ __forceinline__ void cp_commit() {
    asm volatile("cp.async.commit_group;");
}
template<int N> __device__ __forceinline__ void cp_wait() {
    asm volatile("cp.async.wait_group %0;" :: "n"(N));
}

// CTA: 128 threads / 4 warps. Warp w = head kvh*4+w, owns ALL 32 queries of
// the tile (M=32 = two m16 tiles). K/V B-fragments loaded once per warp serve
// 2x the MMAs vs the 8-warp layout -> smem read traffic halved.
__global__ void __launch_bounds__(128, 3)
attn_kernel(const float* __restrict__ Q, float* __restrict__ O)
{
    extern __shared__ __align__(16) __half sm[];
    __half* qhbuf = sm;                    // transient Q staging (overlays stage 0)
    const unsigned kvsm = smem_u32(sm);

    const int tid  = threadIdx.x;
    const int w    = tid >> 5;
    const int lane = tid & 31;
    const int g    = lane >> 2;
    const int t    = lane & 3;
    const int qs   = blockIdx.x * QTILE;
    const int kvh  = blockIdx.y;
    const int b    = blockIdx.z;

    // RoPE Q: fp32 gmem -> fp16 smem (scaled by 0.125*log2e), 1 thread/row
    {
        const int row = tid;                 // head row>>5, query row&31
        const int qg  = qs + (row & 31);
        const float* qp = Q + ((size_t)(b * S_LEN + qg) * QSTRIDE
                               + (kvh * GROUP + (row >> 5)) * HDIM);
        float xv[64], cs[32], sn[32];
        #pragma unroll
        for (int i = 0; i < 16; ++i)
            *reinterpret_cast<float4*>(&xv[4 * i]) = reinterpret_cast<const float4*>(qp)[i];
        const float4* ct4 = reinterpret_cast<const float4*>(g_cos + qg * 32);
        const float4* st4 = reinterpret_cast<const float4*>(g_sin + qg * 32);
        #pragma unroll
        for (int i = 0; i < 8; ++i) {
            *reinterpret_cast<float4*>(&cs[4 * i]) = ct4[i];
            *reinterpret_cast<float4*>(&sn[4 * i]) = st4[i];
        }
        __half2* rowp = reinterpret_cast<__half2*>(qhbuf + row * KROW);
        float r[64];
        #pragma unroll
        for (int d = 0; d < 32; ++d) {
            r[d]      = (xv[d] * cs[d] - xv[d + 32] * sn[d]) * QSCALE;
            r[d + 32] = (xv[d + 32] * cs[d] + xv[d] * sn[d]) * QSCALE;
        }
        #pragma unroll
        for (int j = 0; j < 32; ++j)
            rowp[j] = __floats2half2_rn(r[2 * j], r[2 * j + 1]);
    }
    __syncthreads();

    // persistent Q fragments: 2 m16 tiles per warp
    unsigned qa[2][4][4];
    {
        unsigned qbase = smem_u32(qhbuf);
        int colh = (lane >> 4) * 8;
        #pragma unroll
        for (int mi = 0; mi < 2; ++mi) {
            int row = w * 32 + mi * 16 + (lane & 15);
            #pragma unroll
            for (int ki = 0; ki < 4; ++ki) {
                unsigned a = qbase + (unsigned)((row * KROW + ki * 16 + colh) * 2);
                ldsm_x4(qa[mi][ki][0], qa[mi][ki][1], qa[mi][ki][2], qa[mi][ki][3], a);
            }
        }
    }
    __syncthreads();   // Q read done; stage 0 may overwrite

    float of[2][8][4];
    #pragma unroll
    for (int mi = 0; mi < 2; ++mi)
        #pragma unroll
        for (int n = 0; n < 8; ++n)
            #pragma unroll
            for (int e = 0; e < 4; ++e) of[mi][n][e] = 0.f;
    float lsum[4] = {0.f, 0.f, 0.f, 0.f};   // (mi0,g),(mi0,g+8),(mi1,g),(mi1,g+8)

    const int j0  = (qs >= WIN) ? ((qs - WIN) & ~(NC - 1)) : 0;
    const int nch = (qs + QTILE - j0 + NC - 1) / NC;

    const __half* ksrc = Khalf + ((size_t)(b * KVHEADS + kvh) * S_LEN) * HDIM;
    const __half* vsrc = Vhalf + ((size_t)(b * KVHEADS + kvh) * S_LEN) * HDIM;

    const int kb_key = ((lane >> 4) & 1) * 8 + (lane & 7);
    const int kb_dim = ((lane >> 3) & 1) * 8;
    const int vb_key = ((lane >> 3) & 1) * 8 + (lane & 7);
    const int vb_dim = ((lane >> 4) & 1) * 8;

    auto stage_load = [&](int ci, int s) {
        int c0 = j0 + ci * NC;
        unsigned base = kvsm + (unsigned)(s * STAGE_HALVES * 2);
        #pragma unroll
        for (int it = 0; it < 8; ++it) {
            int idx = tid + it * 128;
            int tensor = idx >> 9;
            int r = (idx >> 3) & 63, p = idx & 7;
            const __half* src = (tensor ? vsrc : ksrc) + (size_t)(c0 + r) * HDIM + p * 8;
            unsigned dst = base + (unsigned)((tensor * NC * KROW + r * KROW + p * 8) * 2);
            cp16(dst, src);
        }
        cp_commit();
    };

    stage_load(0, 0);

    for (int ci = 0; ci < nch; ++ci) {
        if (ci + 1 < nch) { stage_load(ci + 1, (ci + 1) & 1); cp_wait<1>(); }
        else              { cp_wait<0>(); }
        __syncthreads();

        const unsigned ks = kvsm + (unsigned)(((ci & 1) * STAGE_HALVES) * 2);
        const unsigned vs = ks + (unsigned)(NC * KROW * 2);
        const int c0 = j0 + ci * NC;

        unsigned l2[4] = {0u, 0u, 0u, 0u};

        #pragma unroll
        for (int np = 0; np < 4; ++np) {
            const int colbase = c0 + np * 16;
            // uniform skip: all warps own queries qs..qs+31
            if (colbase > qs + 31 || colbase + 15 + WIN < qs) continue;

            unsigned kb[4][4];
            #pragma unroll
            for (int ki = 0; ki < 4; ++ki) {
                unsigned a = ks + (unsigned)((((np * 16 + kb_key) * KROW) + ki * 16 + kb_dim) * 2);
                ldsm_x4(kb[ki][0], kb[ki][1], kb[ki][2], kb[ki][3], a);
            }
            float sf[2][2][4];
            #pragma unroll
            for (int mi = 0; mi < 2; ++mi)
                #pragma unroll
                for (int ni = 0; ni < 2; ++ni)
                    #pragma unroll
                    for (int e = 0; e < 4; ++e) sf[mi][ni][e] = 0.f;
            #pragma unroll
            for (int ki = 0; ki < 4; ++ki) {
                mma16816(sf[0][0], qa[0][ki], kb[ki][0], kb[ki][1]);
                mma16816(sf[0][1], qa[0][ki], kb[ki][2], kb[ki][3]);
                mma16816(sf[1][0], qa[1][ki], kb[ki][0], kb[ki][1]);
                mma16816(sf[1][1], qa[1][ki], kb[ki][2], kb[ki][3]);
            }

            unsigned pa[2][4];
            #pragma unroll
            for (int mi = 0; mi < 2; ++mi) {
                const int qg0 = qs + mi * 16 + g;
                const int qg1 = qg0 + 8;
                const bool full = (colbase + 15 <= qs + mi * 16) &&
                                  (colbase >= qs + mi * 16 + 15 - WIN);
                if (!full) {
                    #pragma unroll
                    for (int ni = 0; ni < 2; ++ni) {
                        int p0 = colbase + ni * 8 + 2 * t;
                        int p1 = p0 + 1;
                        sf[mi][ni][0] = (p0 <= qg0 && p0 + WIN >= qg0) ? sf[mi][ni][0] : -1e30f;
                        sf[mi][ni][1] = (p1 <= qg0 && p1 + WIN >= qg0) ? sf[mi][ni][1] : -1e30f;
                        sf[mi][ni][2] = (p0 <= qg1 && p0 + WIN >= qg1) ? sf[mi][ni][2] : -1e30f;
                        sf[mi][ni][3] = (p1 <= qg1 && p1 + WIN >= qg1) ? sf[mi][ni][3] : -1e30f;
                    }
                }
                #pragma unroll
                for (int ni = 0; ni < 2; ++ni) {
                    pa[mi][ni * 2 + 0] = h2ex2(packh2(sf[mi][ni][0], sf[mi][ni][1]));
                    pa[mi][ni * 2 + 1] = h2ex2(packh2(sf[mi][ni][2], sf[mi][ni][3]));
                    l2[mi * 2 + 0] = hadd2u(l2[mi * 2 + 0], pa[mi][ni * 2 + 0]);
                    l2[mi * 2 + 1] = hadd2u(l2[mi * 2 + 1], pa[mi][ni * 2 + 1]);
                }
            }

            unsigned vb[4][4];
            #pragma unroll
            for (int dp = 0; dp < 4; ++dp) {
                unsigned a = vs + (unsigned)((((np * 16 + vb_key) * KROW) + dp * 16 + vb_dim) * 2);
                ldsm_x4_t(vb[dp][0], vb[dp][1], vb[dp][2], vb[dp][3], a);
            }
            #pragma unroll
            for (int dp = 0; dp < 4; ++dp) {
                mma16816(of[0][2 * dp],     pa[0], vb[dp][0], vb[dp][1]);
                mma16816(of[0][2 * dp + 1], pa[0], vb[dp][2], vb[dp][3]);
                mma16816(of[1][2 * dp],     pa[1], vb[dp][0], vb[dp][1]);
                mma16816(of[1][2 * dp + 1], pa[1], vb[dp][2], vb[dp][3]);
            }
        }

        #pragma unroll
        for (int i = 0; i < 4; ++i) {
            __half2 h = *reinterpret_cast<__half2*>(&l2[i]);
            lsum[i] += __low2float(h) + __high2float(h);
        }
        __syncthreads();
    }

    #pragma unroll
    for (int i = 0; i < 4; ++i) {
        float v = lsum[i];
        v += __shfl_xor_sync(0xffffffffu, v, 1);
        v += __shfl_xor_sync(0xffffffffu, v, 2);
        lsum[i] = 1.f / v;
    }
    const int head = kvh * GROUP + w;
    float* obase = O + (size_t)(b * S_LEN) * QSTRIDE + head * HDIM;
    #pragma unroll
    for (int mi = 0; mi < 2; ++mi) {
        const int r0 = qs + mi * 16 + g;
        const int r1 = r0 + 8;
        #pragma unroll
        for (int n = 0; n < 8; ++n) {
            int col = n * 8 + 2 * t;
            float2 v0 = make_float2(of[mi][n][0] * lsum[mi * 2],
                                    of[mi][n][1] * lsum[mi * 2]);
            float2 v1 = make_float2(of[mi][n][2] * lsum[mi * 2 + 1],
                                    of[mi][n][3] * lsum[mi * 2 + 1]);
            *reinterpret_cast<float2*>(obase + (size_t)r0 * QSTRIDE + col) = v0;
            *reinterpret_cast<float2*>(obase + (size_t)r1 * QSTRIDE + col) = v1;
        }
    }
}

extern "C" void kernel_launch(void* const* d_in, const int* in_sizes, int n_in,
                              void* d_out, int out_size) {
    const float* Q = (const float*)d_in[0];
    const float* K = (const float*)d_in[1];
    const float* V = (const float*)d_in[2];
    float* O = (float*)d_out;

    cudaFuncSetAttribute(attn_kernel, cudaFuncAttributeMaxDynamicSharedMemorySize, SMEM_BYTES);

    prep_kv_kernel<<<(BATCH * S_LEN * KVHEADS * 32 + 255) / 256, 256>>>(K, V);

    dim3 grid(S_LEN / QTILE, KVHEADS, BATCH);
    attn_kernel<<<grid, 128, SMEM_BYTES>>>(Q, O);
}